// round 1
// baseline (speedup 1.0000x reference)
#include <cuda_runtime.h>
#include <math.h>

#define FULLMASK 0xffffffffu

// Precomputed per-launch parameters (deterministic, recomputed every launch)
__device__ float g_trig[64];   // [l][wire][{cy, sy, cz, sz}] half-angle trig
__device__ float g_W1f[128];   // BN folded into W1:  W1f[k][j] = scale_k * W1[k][j]
__device__ float g_b1f[8];     // b1f[j] = b1[j] + sum_k shift_k * W1[k][j]

__global__ void prep_kernel(const float* __restrict__ qw,
                            const float* __restrict__ g,
                            const float* __restrict__ b,
                            const float* __restrict__ rm,
                            const float* __restrict__ rv,
                            const float* __restrict__ W1,
                            const float* __restrict__ b1) {
    __shared__ float s_scale[16];
    __shared__ float s_shift[16];
    int t = threadIdx.x;
    if (t < 16) {
        float sy, cy, sz, cz;
        sincosf(0.5f * qw[t * 2 + 0], &sy, &cy);   // RY(theta)
        sincosf(0.5f * qw[t * 2 + 1], &sz, &cz);   // RZ(phi)
        g_trig[t * 4 + 0] = cy;
        g_trig[t * 4 + 1] = sy;
        g_trig[t * 4 + 2] = cz;
        g_trig[t * 4 + 3] = sz;

        float sc = g[t] * rsqrtf(rv[t] + 1e-5f);
        s_scale[t] = sc;
        s_shift[t] = b[t] - rm[t] * sc;
    }
    __syncthreads();
    if (t < 128) {
        g_W1f[t] = s_scale[t >> 3] * W1[t];
    }
    if (t < 8) {
        float acc = b1[t];
        #pragma unroll
        for (int k = 0; k < 16; ++k) acc += s_shift[k] * W1[k * 8 + t];
        g_b1f[t] = acc;
    }
}

__device__ __forceinline__ float warpsum(float v) {
    #pragma unroll
    for (int o = 16; o > 0; o >>= 1) v += __shfl_xor_sync(FULLMASK, v, o);
    return v;
}

// One warp simulates one sample. Amplitude index i (8 bits, wire w <-> bit 7-w):
//   bits 7..3 = lane, bits 2..0 = register slot r.
__global__ __launch_bounds__(256) void qml_kernel(const float* __restrict__ x,
                                                  const float* __restrict__ W2,
                                                  const float* __restrict__ b2,
                                                  float* __restrict__ out) {
    __shared__ float sTrig[64];
    __shared__ float sW1f[128];
    __shared__ float sb1f[8];
    __shared__ float sW2[16];
    __shared__ float sb2[2];
    __shared__ float shRe[8][256];   // per-warp CNOT-permutation staging
    __shared__ float shIm[8][256];

    int tid = threadIdx.x;
    if (tid < 64) sTrig[tid] = g_trig[tid];
    else if (tid < 192) sW1f[tid - 64] = g_W1f[tid - 64];
    else if (tid < 200) sb1f[tid - 192] = g_b1f[tid - 192];
    else if (tid < 216) sW2[tid - 200] = W2[tid - 200];
    else if (tid < 218) sb2[tid - 216] = b2[tid - 216];
    __syncthreads();

    const int warpid = tid >> 5;
    const int lane = tid & 31;
    const int sample = blockIdx.x * 8 + warpid;

    // Load raw (un-normalized) state: 8 consecutive amplitudes per lane
    const float4* xp = reinterpret_cast<const float4*>(x + (size_t)sample * 256 + lane * 8);
    float4 v0 = xp[0];
    float4 v1 = xp[1];
    float ar[8] = {v0.x, v0.y, v0.z, v0.w, v1.x, v1.y, v1.z, v1.w};
    float ai[8] = {0.f, 0.f, 0.f, 0.f, 0.f, 0.f, 0.f, 0.f};

    float nrm2 = 0.f;
    #pragma unroll
    for (int r = 0; r < 8; ++r) nrm2 += ar[r] * ar[r];
    nrm2 = warpsum(nrm2);
    const float inv = 1.0f / nrm2;

    #pragma unroll
    for (int l = 0; l < 2; ++l) {
        #pragma unroll
        for (int w = 0; w < 8; ++w) {
            const int gi = (l * 8 + w) * 4;
            const float cy = sTrig[gi + 0];
            const float sy = sTrig[gi + 1];
            const float cz = sTrig[gi + 2];
            const float sz = sTrig[gi + 3];
            const int bit = 7 - w;

            if (bit >= 3) {
                // RY on a lane bit: partner via shfl_xor
                const int lmask = 1 << (bit - 3);
                const float se = (lane & lmask) ? sy : -sy;
                #pragma unroll
                for (int r = 0; r < 8; ++r) {
                    float br = __shfl_xor_sync(FULLMASK, ar[r], lmask);
                    float bi = __shfl_xor_sync(FULLMASK, ai[r], lmask);
                    ar[r] = cy * ar[r] + se * br;
                    ai[r] = cy * ai[r] + se * bi;
                }
                // RZ: diagonal phase, sign from lane bit
                const float sze = (lane & lmask) ? sz : -sz;
                #pragma unroll
                for (int r = 0; r < 8; ++r) {
                    float re = ar[r], im = ai[r];
                    ar[r] = cz * re - sze * im;
                    ai[r] = cz * im + sze * re;
                }
            } else {
                // RY on a register bit: pairs within the lane
                const int m = 1 << bit;
                #pragma unroll
                for (int r0 = 0; r0 < 8; ++r0) {
                    if (!(r0 & m)) {
                        const int r1 = r0 | m;
                        float a0 = ar[r0], a1 = ar[r1];
                        ar[r0] = cy * a0 - sy * a1;
                        ar[r1] = sy * a0 + cy * a1;
                        float c0 = ai[r0], c1 = ai[r1];
                        ai[r0] = cy * c0 - sy * c1;
                        ai[r1] = sy * c0 + cy * c1;
                    }
                }
                #pragma unroll
                for (int r = 0; r < 8; ++r) {
                    const float sze = (r & m) ? sz : -sz;
                    float re = ar[r], im = ai[r];
                    ar[r] = cz * re - sze * im;
                    ai[r] = cz * im + sze * re;
                }
            }
        }

        // CNOT chain (ctrl i -> tgt i+1, i=0..6) composes to the permutation
        //   new[j] = old[j ^ (j >> 1)]
        // Staged through shared with a conflict-free [r*32+lane] layout.
        __syncwarp();
        #pragma unroll
        for (int r = 0; r < 8; ++r) {
            shRe[warpid][r * 32 + lane] = ar[r];
            shIm[warpid][r * 32 + lane] = ai[r];
        }
        __syncwarp();
        #pragma unroll
        for (int r = 0; r < 8; ++r) {
            int i = (lane << 3) | r;
            int m2 = i ^ (i >> 1);
            ar[r] = shRe[warpid][(m2 & 7) * 32 + (m2 >> 3)];
            ai[r] = shIm[warpid][(m2 & 7) * 32 + (m2 >> 3)];
        }
    }

    // ---- Measurements (on un-normalized state; scale by inv at the end) ----
    float p[8];
    float sump = 0.f;
    #pragma unroll
    for (int r = 0; r < 8; ++r) {
        p[r] = ar[r] * ar[r] + ai[r] * ai[r];
        sump += p[r];
    }

    float q[16];

    // Z on wires 0..4 (lane bits 4..0)
    #pragma unroll
    for (int w = 0; w < 5; ++w) {
        float v = (lane & (1 << (4 - w))) ? -sump : sump;
        q[w] = warpsum(v);
    }
    // Z on wires 5..7 (register bits 2..0)
    #pragma unroll
    for (int w = 5; w < 8; ++w) {
        const int m = 1 << (7 - w);
        float v = 0.f;
        #pragma unroll
        for (int r = 0; r < 8; ++r) v += (r & m) ? -p[r] : p[r];
        q[w] = warpsum(v);
    }
    // X on wires 0..4: sum over ALL j of s_j * s_{j^mask} == 2*sum over pairs
    #pragma unroll
    for (int w = 0; w < 5; ++w) {
        const int lmask = 1 << (4 - w);
        float v = 0.f;
        #pragma unroll
        for (int r = 0; r < 8; ++r) {
            float br = __shfl_xor_sync(FULLMASK, ar[r], lmask);
            float bi = __shfl_xor_sync(FULLMASK, ai[r], lmask);
            v += ar[r] * br + ai[r] * bi;
        }
        q[8 + w] = warpsum(v);
    }
    // X on wires 5..7: in-register pairs, explicit factor 2
    #pragma unroll
    for (int w = 5; w < 8; ++w) {
        const int m = 1 << (7 - w);
        float v = 0.f;
        #pragma unroll
        for (int r0 = 0; r0 < 8; ++r0) {
            if (!(r0 & m)) {
                const int r1 = r0 | m;
                v += 2.0f * (ar[r0] * ar[r1] + ai[r0] * ai[r1]);
            }
        }
        q[8 + w] = warpsum(v);
    }

    // ---- BN (folded) + MLP on lane 0 ----
    if (lane == 0) {
        float qn[16];
        #pragma unroll
        for (int k = 0; k < 16; ++k) qn[k] = q[k] * inv;

        float h[8];
        #pragma unroll
        for (int j = 0; j < 8; ++j) {
            float acc = sb1f[j];
            #pragma unroll
            for (int k = 0; k < 16; ++k) acc += qn[k] * sW1f[k * 8 + j];
            h[j] = fmaxf(acc, 0.f);
        }
        float o0 = sb2[0];
        float o1 = sb2[1];
        #pragma unroll
        for (int j = 0; j < 8; ++j) {
            o0 += h[j] * sW2[j * 2 + 0];
            o1 += h[j] * sW2[j * 2 + 1];
        }
        out[(size_t)sample * 2 + 0] = o0;
        out[(size_t)sample * 2 + 1] = o1;
    }
}

extern "C" void kernel_launch(void* const* d_in, const int* in_sizes, int n_in,
                              void* d_out, int out_size) {
    const float* x  = (const float*)d_in[0];
    const float* qw = (const float*)d_in[1];
    const float* g  = (const float*)d_in[2];
    const float* b  = (const float*)d_in[3];
    const float* rm = (const float*)d_in[4];
    const float* rv = (const float*)d_in[5];
    const float* W1 = (const float*)d_in[6];
    const float* b1 = (const float*)d_in[7];
    const float* W2 = (const float*)d_in[8];
    const float* b2 = (const float*)d_in[9];
    float* out = (float*)d_out;

    prep_kernel<<<1, 128>>>(qw, g, b, rm, rv, W1, b1);
    qml_kernel<<<8192, 256>>>(x, W2, b2, out);
}

// round 7
// speedup vs baseline: 1.3898x; 1.3898x over previous
#include <cuda_runtime.h>

#define FULLMASK 0xffffffffu
typedef unsigned long long ull;

// ---------------- packed f32x2 helpers ----------------
__device__ __forceinline__ ull pk(float lo, float hi) {
    ull r; asm("mov.b64 %0, {%1, %2};" : "=l"(r) : "f"(lo), "f"(hi)); return r;
}
__device__ __forceinline__ void upk(ull v, float &lo, float &hi) {
    asm("mov.b64 {%0, %1}, %2;" : "=f"(lo), "=f"(hi) : "l"(v));
}
__device__ __forceinline__ ull fma2(ull a, ull b, ull c) {
    ull d; asm("fma.rn.f32x2 %0, %1, %2, %3;" : "=l"(d) : "l"(a), "l"(b), "l"(c)); return d;
}
__device__ __forceinline__ ull mul2(ull a, ull b) {
    ull d; asm("mul.rn.f32x2 %0, %1, %2;" : "=l"(d) : "l"(a), "l"(b)); return d;
}
__device__ __forceinline__ ull shfl2(ull v, int lm) {
    float lo, hi; upk(v, lo, hi);
    lo = __shfl_xor_sync(FULLMASK, lo, lm);
    hi = __shfl_xor_sync(FULLMASK, hi, lm);
    return pk(lo, hi);
}

// ---------------- precomputed params ----------------
__device__ float  g_ry[32];      // [gate 0..15][cy,sy]
__device__ float2 g_phase[512];  // [l*256 + slot], slot = (k&7)*32 + (k>>3), plain theta(k)
__device__ float  g_W1f[128];    // BN folded into W1
__device__ float  g_b1f[8];

__global__ void prep_kernel(const float* __restrict__ qw,
                            const float* __restrict__ g,
                            const float* __restrict__ b,
                            const float* __restrict__ rm,
                            const float* __restrict__ rv,
                            const float* __restrict__ W1,
                            const float* __restrict__ b1) {
    __shared__ float s_phi[16];
    __shared__ float s_scale[16], s_shift[16];
    int t = threadIdx.x;
    if (t < 16) {
        float sy, cy;
        sincosf(0.5f * qw[t * 2 + 0], &sy, &cy);       // RY half-angle
        g_ry[t * 2 + 0] = cy; g_ry[t * 2 + 1] = sy;
        s_phi[t] = 0.5f * qw[t * 2 + 1];               // RZ half-angle
        float sc = g[t] * rsqrtf(rv[t] + 1e-5f);
        s_scale[t] = sc;
        s_shift[t] = b[t] - rm[t] * sc;
    }
    __syncthreads();
    {
        // Plain phase tables: theta_l(k) = sum_w (bit(7-w) of k ? +phi : -phi).
        // RZs are applied at end of each layer, BEFORE that layer's CNOT chain,
        // so no permutation remap is needed.
        int k = t;
        float th0 = 0.f, th1 = 0.f;
        #pragma unroll
        for (int w = 0; w < 8; ++w) {
            int bit = 7 - w;
            th0 += ((k >> bit) & 1) ? s_phi[w]     : -s_phi[w];
            th1 += ((k >> bit) & 1) ? s_phi[8 + w] : -s_phi[8 + w];
        }
        float c0, s0, c1, s1;
        sincosf(th0, &s0, &c0);
        sincosf(th1, &s1, &c1);
        int slot = (k & 7) * 32 + (k >> 3);
        g_phase[slot]       = make_float2(c0, s0);
        g_phase[256 + slot] = make_float2(c1, s1);
    }
    if (t < 128) g_W1f[t] = s_scale[t >> 3] * W1[t];
    if (t < 8) {
        float acc = b1[t];
        #pragma unroll
        for (int kk = 0; kk < 16; ++kk) acc += s_shift[kk] * W1[kk * 8 + t];
        g_b1f[t] = acc;
    }
}

// One warp per sample. Amplitude index k (8 bits, wire w <-> bit 7-w):
//   bits 7..3 = lane, bits 2..0 = reg slot r.
// CNOT chains applied explicitly via shared staging: new[j] = old[j ^ (j>>1)]
// (round-1 HW-verified pattern). Measurements in plain index space.
__global__ __launch_bounds__(256) void qml_kernel(const float* __restrict__ x,
                                                  const float* __restrict__ W2,
                                                  const float* __restrict__ b2,
                                                  float* __restrict__ out) {
    __shared__ float2 sPh[512];
    __shared__ float  sRy[32];
    __shared__ float  sW1f[128];
    __shared__ float  sb1f[8];
    __shared__ float  sW2[16];
    __shared__ float  sb2[2];
    __shared__ ull    stg[8][256];    // per-warp CNOT permutation staging (packed re,im)
    __shared__ float  red[8][8][17];

    int tid = threadIdx.x;
    {
        sPh[tid]       = g_phase[tid];
        sPh[tid + 256] = g_phase[tid + 256];
        if (tid < 32)        sRy[tid] = g_ry[tid];
        else if (tid < 160)  sW1f[tid - 32] = g_W1f[tid - 32];
        else if (tid < 168)  sb1f[tid - 160] = g_b1f[tid - 160];
        else if (tid < 184)  sW2[tid - 168] = W2[tid - 168];
        else if (tid < 186)  sb2[tid - 184] = b2[tid - 184];
    }
    __syncthreads();

    const int warpid = tid >> 5;
    const int lane = tid & 31;
    const int sample = blockIdx.x * 8 + warpid;

    // ---- load (un-normalized); track ||x||^2 as extra reduction feature ----
    const float4* xp = reinterpret_cast<const float4*>(x + (size_t)sample * 256 + lane * 8);
    float4 v0 = xp[0];
    float4 v1 = xp[1];
    float a0 = v0.x, a1 = v0.y, a2 = v0.z, a3 = v0.w;
    float a4 = v1.x, a5 = v1.y, a6 = v1.z, a7 = v1.w;
    float nrm2 = a0*a0 + a1*a1 + a2*a2 + a3*a3 + a4*a4 + a5*a5 + a6*a6 + a7*a7;

    // ---- Layer 1 RYs (state real). Pack (a[r], a[r+4]) into f32x2 lo/hi. ----
    ull z[4] = { pk(a0, a4), pk(a1, a5), pk(a2, a6), pk(a3, a7) };

    // wires 0..4: lane-bit gates, lmask 16,8,4,2,1
    #pragma unroll
    for (int w = 0; w < 5; ++w) {
        const int lmask = 1 << (4 - w);
        const float cy = sRy[w * 2], sy = sRy[w * 2 + 1];
        const float se = (lane & lmask) ? sy : -sy;
        const ull cy2 = pk(cy, cy), se2 = pk(se, se);
        #pragma unroll
        for (int i = 0; i < 4; ++i) {
            ull bp = shfl2(z[i], lmask);
            z[i] = fma2(cy2, z[i], mul2(se2, bp));
        }
    }
    // wire 5 (bit2): pairs are (lo,hi) within each packed register
    {
        const float cy = sRy[10], sy = sRy[11];
        #pragma unroll
        for (int i = 0; i < 4; ++i) {
            float e0, e1; upk(z[i], e0, e1);
            z[i] = pk(cy * e0 - sy * e1, sy * e0 + cy * e1);
        }
    }
    // wire 6 (bit1): pack-pairs (z0,z2), (z1,z3)
    {
        const float cy = sRy[12], sy = sRy[13];
        const ull cy2 = pk(cy, cy), sp2 = pk(sy, sy), sn2 = pk(-sy, -sy);
        ull t0 = z[0], t1 = z[1];
        z[0] = fma2(cy2, z[0], mul2(sn2, z[2]));
        z[2] = fma2(cy2, z[2], mul2(sp2, t0));
        z[1] = fma2(cy2, z[1], mul2(sn2, z[3]));
        z[3] = fma2(cy2, z[3], mul2(sp2, t1));
    }
    // wire 7 (bit0): pack-pairs (z0,z1), (z2,z3)
    {
        const float cy = sRy[14], sy = sRy[15];
        const ull cy2 = pk(cy, cy), sp2 = pk(sy, sy), sn2 = pk(-sy, -sy);
        ull t0 = z[0], t2 = z[2];
        z[0] = fma2(cy2, z[0], mul2(sn2, z[1]));
        z[1] = fma2(cy2, z[1], mul2(sp2, t0));
        z[2] = fma2(cy2, z[2], mul2(sn2, z[3]));
        z[3] = fma2(cy2, z[3], mul2(sp2, t2));
    }

    // ---- Layer-1 RZ phases: state -> complex (re, im) packed per amplitude ----
    ull s[8];
    {
        float b0_, b4_; upk(z[0], b0_, b4_);
        float b1_, b5_; upk(z[1], b1_, b5_);
        float b2_, b6_; upk(z[2], b2_, b6_);
        float b3_, b7_; upk(z[3], b3_, b7_);
        float ar[8] = { b0_, b1_, b2_, b3_, b4_, b5_, b6_, b7_ };
        #pragma unroll
        for (int r = 0; r < 8; ++r) {
            float2 ph = sPh[r * 32 + lane];
            s[r] = pk(ar[r] * ph.x, ar[r] * ph.y);
        }
    }

    // ---- CNOT chain #1: new[j] = old[j ^ (j>>1)] via shared staging ----
    __syncwarp();
    #pragma unroll
    for (int r = 0; r < 8; ++r) stg[warpid][r * 32 + lane] = s[r];
    __syncwarp();
    #pragma unroll
    for (int r = 0; r < 8; ++r) {
        int i = (lane << 3) | r;
        int m = i ^ (i >> 1);
        s[r] = stg[warpid][(m & 7) * 32 + (m >> 3)];
    }

    // ---- Layer 2 RYs (complex, plain index space) ----
    // wires 0..4: lane-bit gates
    #pragma unroll
    for (int w = 0; w < 5; ++w) {
        const int lmask = 1 << (4 - w);
        const float cy = sRy[16 + w * 2], sy = sRy[16 + w * 2 + 1];
        const float se = (lane & lmask) ? sy : -sy;
        const ull cy2 = pk(cy, cy), se2 = pk(se, se);
        #pragma unroll
        for (int r = 0; r < 8; ++r) {
            ull bp = shfl2(s[r], lmask);
            s[r] = fma2(cy2, s[r], mul2(se2, bp));
        }
    }
    // wire 5 (bit2): pairs (r, r^4)
    {
        const float cy = sRy[26], sy = sRy[27];
        const ull cy2 = pk(cy, cy), sp2 = pk(sy, sy), sn2 = pk(-sy, -sy);
        ull t;
        t = s[0]; s[0] = fma2(cy2, s[0], mul2(sn2, s[4])); s[4] = fma2(cy2, s[4], mul2(sp2, t));
        t = s[1]; s[1] = fma2(cy2, s[1], mul2(sn2, s[5])); s[5] = fma2(cy2, s[5], mul2(sp2, t));
        t = s[2]; s[2] = fma2(cy2, s[2], mul2(sn2, s[6])); s[6] = fma2(cy2, s[6], mul2(sp2, t));
        t = s[3]; s[3] = fma2(cy2, s[3], mul2(sn2, s[7])); s[7] = fma2(cy2, s[7], mul2(sp2, t));
    }
    // wire 6 (bit1): pairs (r, r^2)
    {
        const float cy = sRy[28], sy = sRy[29];
        const ull cy2 = pk(cy, cy), sp2 = pk(sy, sy), sn2 = pk(-sy, -sy);
        ull t;
        t = s[0]; s[0] = fma2(cy2, s[0], mul2(sn2, s[2])); s[2] = fma2(cy2, s[2], mul2(sp2, t));
        t = s[1]; s[1] = fma2(cy2, s[1], mul2(sn2, s[3])); s[3] = fma2(cy2, s[3], mul2(sp2, t));
        t = s[4]; s[4] = fma2(cy2, s[4], mul2(sn2, s[6])); s[6] = fma2(cy2, s[6], mul2(sp2, t));
        t = s[5]; s[5] = fma2(cy2, s[5], mul2(sn2, s[7])); s[7] = fma2(cy2, s[7], mul2(sp2, t));
    }
    // wire 7 (bit0): pairs (r, r^1)
    {
        const float cy = sRy[30], sy = sRy[31];
        const ull cy2 = pk(cy, cy), sp2 = pk(sy, sy), sn2 = pk(-sy, -sy);
        ull t;
        t = s[0]; s[0] = fma2(cy2, s[0], mul2(sn2, s[1])); s[1] = fma2(cy2, s[1], mul2(sp2, t));
        t = s[2]; s[2] = fma2(cy2, s[2], mul2(sn2, s[3])); s[3] = fma2(cy2, s[3], mul2(sp2, t));
        t = s[4]; s[4] = fma2(cy2, s[4], mul2(sn2, s[5])); s[5] = fma2(cy2, s[5], mul2(sp2, t));
        t = s[6]; s[6] = fma2(cy2, s[6], mul2(sn2, s[7])); s[7] = fma2(cy2, s[7], mul2(sp2, t));
    }
    // ---- Layer-2 RZ phases (complex multiply) ----
    #pragma unroll
    for (int r = 0; r < 8; ++r) {
        float2 ph = sPh[256 + r * 32 + lane];
        float re, im; upk(s[r], re, im);
        s[r] = pk(ph.x * re - ph.y * im, ph.x * im + ph.y * re);
    }

    // ---- CNOT chain #2: same permutation via shared staging ----
    __syncwarp();
    #pragma unroll
    for (int r = 0; r < 8; ++r) stg[warpid][r * 32 + lane] = s[r];
    __syncwarp();
    #pragma unroll
    for (int r = 0; r < 8; ++r) {
        int i = (lane << 3) | r;
        int m = i ^ (i >> 1);
        s[r] = stg[warpid][(m & 7) * 32 + (m >> 3)];
    }

    // ---- Measurements (plain index space, round-1 verified masks) ----
    float p[8], sump = 0.f;
    #pragma unroll
    for (int r = 0; r < 8; ++r) {
        float lo, hi; upk(mul2(s[r], s[r]), lo, hi);
        p[r] = lo + hi;
        sump += p[r];
    }

    float q[17];
    // Z wires 0..4: sign from lane bit (16 >> w)
    #pragma unroll
    for (int w = 0; w < 5; ++w) {
        q[w] = (lane & (1 << (4 - w))) ? -sump : sump;
    }
    // Z wires 5..7: sign from reg bit
    q[5] = (p[0] + p[1] + p[2] + p[3]) - (p[4] + p[5] + p[6] + p[7]);   // bit2
    q[6] = (p[0] + p[1] - p[2] - p[3]) + (p[4] + p[5] - p[6] - p[7]);   // bit1
    q[7] = (p[0] - p[1] + p[2] - p[3]) + (p[4] - p[5] + p[6] - p[7]);   // bit0

    // X wires 0..4: sum over all j of s_j . s_{j^lmask} (counts each pair twice)
    #pragma unroll
    for (int w = 0; w < 5; ++w) {
        const int lmask = 1 << (4 - w);
        ull acc = pk(0.f, 0.f);
        #pragma unroll
        for (int r = 0; r < 8; ++r) {
            ull bp = shfl2(s[r], lmask);
            acc = fma2(s[r], bp, acc);
        }
        float lo, hi; upk(acc, lo, hi);
        q[8 + w] = lo + hi;
    }
    // X wire 5 (bit2): pairs (r, r^4), factor 2
    {
        ull acc = fma2(s[0], s[4], mul2(s[1], s[5]));
        acc = fma2(s[2], s[6], acc);
        acc = fma2(s[3], s[7], acc);
        float lo, hi; upk(acc, lo, hi);
        q[13] = 2.f * (lo + hi);
    }
    // X wire 6 (bit1): pairs (r, r^2)
    {
        ull acc = fma2(s[0], s[2], mul2(s[1], s[3]));
        acc = fma2(s[4], s[6], acc);
        acc = fma2(s[5], s[7], acc);
        float lo, hi; upk(acc, lo, hi);
        q[14] = 2.f * (lo + hi);
    }
    // X wire 7 (bit0): pairs (r, r^1)
    {
        ull acc = fma2(s[0], s[1], mul2(s[2], s[3]));
        acc = fma2(s[4], s[5], acc);
        acc = fma2(s[6], s[7], acc);
        float lo, hi; upk(acc, lo, hi);
        q[15] = 2.f * (lo + hi);
    }
    q[16] = nrm2;

    // ---- Reduce 17 features across the warp: 2 butterfly steps + shared transpose ----
    #pragma unroll
    for (int f = 0; f < 17; ++f) {
        q[f] += __shfl_xor_sync(FULLMASK, q[f], 16);
        q[f] += __shfl_xor_sync(FULLMASK, q[f], 8);
    }
    if (lane < 8) {
        #pragma unroll
        for (int f = 0; f < 17; ++f) red[warpid][lane][f] = q[f];
    }
    __syncwarp();
    float tot = 0.f;
    if (lane < 17) {
        #pragma unroll
        for (int l = 0; l < 8; ++l) tot += red[warpid][l][lane];
    }

    // ---- BN-folded MLP, lane-parallel ----
    float nrm = __shfl_sync(FULLMASK, tot, 16);
    float inv = 1.0f / nrm;
    float qv = tot * inv;            // valid on lanes 0..15

    const int j = lane & 7;
    float acc = sb1f[j];
    #pragma unroll
    for (int f = 0; f < 16; ++f) {
        float qf = __shfl_sync(FULLMASK, qv, f);
        acc = fmaf(qf, sW1f[f * 8 + j], acc);
    }
    float h = fmaxf(acc, 0.f);
    float o0 = h * sW2[j * 2 + 0];
    float o1 = h * sW2[j * 2 + 1];
    #pragma unroll
    for (int off = 4; off > 0; off >>= 1) {
        o0 += __shfl_xor_sync(FULLMASK, o0, off);
        o1 += __shfl_xor_sync(FULLMASK, o1, off);
    }
    if (lane == 0) {
        float2* op = reinterpret_cast<float2*>(out + (size_t)sample * 2);
        *op = make_float2(o0 + sb2[0], o1 + sb2[1]);
    }
}

extern "C" void kernel_launch(void* const* d_in, const int* in_sizes, int n_in,
                              void* d_out, int out_size) {
    const float* x  = (const float*)d_in[0];
    const float* qw = (const float*)d_in[1];
    const float* g  = (const float*)d_in[2];
    const float* b  = (const float*)d_in[3];
    const float* rm = (const float*)d_in[4];
    const float* rv = (const float*)d_in[5];
    const float* W1 = (const float*)d_in[6];
    const float* b1 = (const float*)d_in[7];
    const float* W2 = (const float*)d_in[8];
    const float* b2 = (const float*)d_in[9];
    float* out = (float*)d_out;

    prep_kernel<<<1, 256>>>(qw, g, b, rm, rv, W1, b1);
    qml_kernel<<<8192, 256>>>(x, W2, b2, out);
}

// round 8
// speedup vs baseline: 1.4787x; 1.0640x over previous
#include <cuda_runtime.h>

#define FULLMASK 0xffffffffu
typedef unsigned long long ull;

// ---------------- packed f32x2 helpers ----------------
__device__ __forceinline__ ull pk(float lo, float hi) {
    ull r; asm("mov.b64 %0, {%1, %2};" : "=l"(r) : "f"(lo), "f"(hi)); return r;
}
__device__ __forceinline__ void upk(ull v, float &lo, float &hi) {
    asm("mov.b64 {%0, %1}, %2;" : "=f"(lo), "=f"(hi) : "l"(v));
}
__device__ __forceinline__ ull fma2(ull a, ull b, ull c) {
    ull d; asm("fma.rn.f32x2 %0, %1, %2, %3;" : "=l"(d) : "l"(a), "l"(b), "l"(c)); return d;
}
__device__ __forceinline__ ull mul2(ull a, ull b) {
    ull d; asm("mul.rn.f32x2 %0, %1, %2;" : "=l"(d) : "l"(a), "l"(b)); return d;
}
__device__ __forceinline__ ull shfl2(ull v, int lm) {
    float lo, hi; upk(v, lo, hi);
    lo = __shfl_xor_sync(FULLMASK, lo, lm);
    hi = __shfl_xor_sync(FULLMASK, hi, lm);
    return pk(lo, hi);
}
__device__ __forceinline__ ull shfl2i(ull v, int src) {
    float lo, hi; upk(v, lo, hi);
    lo = __shfl_sync(FULLMASK, lo, src);
    hi = __shfl_sync(FULLMASK, hi, src);
    return pk(lo, hi);
}

// ---------------- precomputed params ----------------
__device__ float  g_ry[32];      // [gate 0..15][cy,sy]
__device__ float2 g_phase[512];  // [l*256 + slot], slot = (k&7)*32 + (k>>3), plain theta(k)
__device__ float  g_W1f[128];    // BN folded into W1
__device__ float  g_b1f[8];

__global__ void prep_kernel(const float* __restrict__ qw,
                            const float* __restrict__ g,
                            const float* __restrict__ b,
                            const float* __restrict__ rm,
                            const float* __restrict__ rv,
                            const float* __restrict__ W1,
                            const float* __restrict__ b1) {
    __shared__ float s_phi[16];
    __shared__ float s_scale[16], s_shift[16];
    int t = threadIdx.x;
    if (t < 16) {
        float sy, cy;
        sincosf(0.5f * qw[t * 2 + 0], &sy, &cy);       // RY half-angle
        g_ry[t * 2 + 0] = cy; g_ry[t * 2 + 1] = sy;
        s_phi[t] = 0.5f * qw[t * 2 + 1];               // RZ half-angle
        float sc = g[t] * rsqrtf(rv[t] + 1e-5f);
        s_scale[t] = sc;
        s_shift[t] = b[t] - rm[t] * sc;
    }
    __syncthreads();
    {
        // Plain phase tables: theta_l(k) = sum_w (bit(7-w) of k ? +phi : -phi).
        // RZs applied at end of each layer, BEFORE that layer's CNOT chain.
        int k = t;
        float th0 = 0.f, th1 = 0.f;
        #pragma unroll
        for (int w = 0; w < 8; ++w) {
            int bit = 7 - w;
            th0 += ((k >> bit) & 1) ? s_phi[w]     : -s_phi[w];
            th1 += ((k >> bit) & 1) ? s_phi[8 + w] : -s_phi[8 + w];
        }
        float c0, s0, c1, s1;
        sincosf(th0, &s0, &c0);
        sincosf(th1, &s1, &c1);
        int slot = (k & 7) * 32 + (k >> 3);
        g_phase[slot]       = make_float2(c0, s0);
        g_phase[256 + slot] = make_float2(c1, s1);
    }
    if (t < 128) g_W1f[t] = s_scale[t >> 3] * W1[t];
    if (t < 8) {
        float acc = b1[t];
        #pragma unroll
        for (int kk = 0; kk < 16; ++kk) acc += s_shift[kk] * W1[kk * 8 + t];
        g_b1f[t] = acc;
    }
}

// One warp per sample. Amplitude index k (8 bits, wire w <-> bit 7-w):
//   bits 7..3 = lane, bits 2..0 = reg slot r.
// CNOT chain permutation new[i] = old[i ^ (i>>1)] done entirely with
// idx-mode shuffles (no shared staging):
//   srcLane = L ^ (L>>1); src reg = rm(r) ^ ((popc(src)&1)<<2), rm = r^(r>>1).
__global__ __launch_bounds__(256) void qml_kernel(const float* __restrict__ x,
                                                  const float* __restrict__ W2,
                                                  const float* __restrict__ b2,
                                                  float* __restrict__ out) {
    __shared__ float2 sPh[512];
    __shared__ float  sRy[32];
    __shared__ float  sW1f[128];
    __shared__ float  sb1f[8];
    __shared__ float  sW2[16];
    __shared__ float  sb2[2];
    __shared__ float  red[8][8][17];

    int tid = threadIdx.x;
    {
        sPh[tid]       = g_phase[tid];
        sPh[tid + 256] = g_phase[tid + 256];
        if (tid < 32)        sRy[tid] = g_ry[tid];
        else if (tid < 160)  sW1f[tid - 32] = g_W1f[tid - 32];
        else if (tid < 168)  sb1f[tid - 160] = g_b1f[tid - 160];
        else if (tid < 184)  sW2[tid - 168] = W2[tid - 168];
        else if (tid < 186)  sb2[tid - 184] = b2[tid - 184];
    }
    __syncthreads();

    const int warpid = tid >> 5;
    const int lane = tid & 31;
    const int sample = blockIdx.x * 8 + warpid;

    // Permutation constants (per lane, reused for both CNOT chains)
    const int psrc = (lane ^ (lane >> 1)) & 31;   // lane to read from
    const int myp  = __popc(lane) & 1;            // L0 of my unique reader

    // ---- load (un-normalized); track ||x||^2 as extra reduction feature ----
    const float4* xp = reinterpret_cast<const float4*>(x + (size_t)sample * 256 + lane * 8);
    float4 v0 = xp[0];
    float4 v1 = xp[1];
    float a0 = v0.x, a1 = v0.y, a2 = v0.z, a3 = v0.w;
    float a4 = v1.x, a5 = v1.y, a6 = v1.z, a7 = v1.w;
    float nrm2 = a0*a0 + a1*a1 + a2*a2 + a3*a3 + a4*a4 + a5*a5 + a6*a6 + a7*a7;

    // ---- Layer 1 RYs (state real). Pack (a[r], a[r+4]) into f32x2 lo/hi. ----
    ull z[4] = { pk(a0, a4), pk(a1, a5), pk(a2, a6), pk(a3, a7) };

    // wires 0..4: lane-bit gates, lmask 16,8,4,2,1
    #pragma unroll
    for (int w = 0; w < 5; ++w) {
        const int lmask = 1 << (4 - w);
        const float cy = sRy[w * 2], sy = sRy[w * 2 + 1];
        const float se = (lane & lmask) ? sy : -sy;
        const ull cy2 = pk(cy, cy), se2 = pk(se, se);
        #pragma unroll
        for (int i = 0; i < 4; ++i) {
            ull bp = shfl2(z[i], lmask);
            z[i] = fma2(cy2, z[i], mul2(se2, bp));
        }
    }
    // wire 5 (bit2): pairs are (lo,hi) within each packed register
    {
        const float cy = sRy[10], sy = sRy[11];
        #pragma unroll
        for (int i = 0; i < 4; ++i) {
            float e0, e1; upk(z[i], e0, e1);
            z[i] = pk(cy * e0 - sy * e1, sy * e0 + cy * e1);
        }
    }
    // wire 6 (bit1): pack-pairs (z0,z2), (z1,z3)
    {
        const float cy = sRy[12], sy = sRy[13];
        const ull cy2 = pk(cy, cy), sp2 = pk(sy, sy), sn2 = pk(-sy, -sy);
        ull t0 = z[0], t1 = z[1];
        z[0] = fma2(cy2, z[0], mul2(sn2, z[2]));
        z[2] = fma2(cy2, z[2], mul2(sp2, t0));
        z[1] = fma2(cy2, z[1], mul2(sn2, z[3]));
        z[3] = fma2(cy2, z[3], mul2(sp2, t1));
    }
    // wire 7 (bit0): pack-pairs (z0,z1), (z2,z3)
    {
        const float cy = sRy[14], sy = sRy[15];
        const ull cy2 = pk(cy, cy), sp2 = pk(sy, sy), sn2 = pk(-sy, -sy);
        ull t0 = z[0], t2 = z[2];
        z[0] = fma2(cy2, z[0], mul2(sn2, z[1]));
        z[1] = fma2(cy2, z[1], mul2(sp2, t0));
        z[2] = fma2(cy2, z[2], mul2(sn2, z[3]));
        z[3] = fma2(cy2, z[3], mul2(sp2, t2));
    }

    // ---- Layer-1 RZ phases: state -> complex (re, im) packed per amplitude ----
    ull s[8];
    {
        float b0_, b4_; upk(z[0], b0_, b4_);
        float b1_, b5_; upk(z[1], b1_, b5_);
        float b2_, b6_; upk(z[2], b2_, b6_);
        float b3_, b7_; upk(z[3], b3_, b7_);
        float ar[8] = { b0_, b1_, b2_, b3_, b4_, b5_, b6_, b7_ };
        #pragma unroll
        for (int r = 0; r < 8; ++r) {
            float2 ph = sPh[r * 32 + lane];
            s[r] = pk(ar[r] * ph.x, ar[r] * ph.y);
        }
    }

    // ---- CNOT chain #1: new[i] = old[i^(i>>1)] via idx shuffles ----
    {
        ull t[8];
        t[0] = myp ? s[4] : s[0];
        t[1] = myp ? s[5] : s[1];
        t[2] = myp ? s[7] : s[3];
        t[3] = myp ? s[6] : s[2];
        t[4] = myp ? s[2] : s[6];
        t[5] = myp ? s[3] : s[7];
        t[6] = myp ? s[1] : s[5];
        t[7] = myp ? s[0] : s[4];
        #pragma unroll
        for (int r = 0; r < 8; ++r) s[r] = shfl2i(t[r], psrc);
    }

    // ---- Layer 2 RYs (complex, plain index space) ----
    // wires 0..4: lane-bit gates
    #pragma unroll
    for (int w = 0; w < 5; ++w) {
        const int lmask = 1 << (4 - w);
        const float cy = sRy[16 + w * 2], sy = sRy[16 + w * 2 + 1];
        const float se = (lane & lmask) ? sy : -sy;
        const ull cy2 = pk(cy, cy), se2 = pk(se, se);
        #pragma unroll
        for (int r = 0; r < 8; ++r) {
            ull bp = shfl2(s[r], lmask);
            s[r] = fma2(cy2, s[r], mul2(se2, bp));
        }
    }
    // wire 5 (bit2): pairs (r, r^4)
    {
        const float cy = sRy[26], sy = sRy[27];
        const ull cy2 = pk(cy, cy), sp2 = pk(sy, sy), sn2 = pk(-sy, -sy);
        ull t;
        t = s[0]; s[0] = fma2(cy2, s[0], mul2(sn2, s[4])); s[4] = fma2(cy2, s[4], mul2(sp2, t));
        t = s[1]; s[1] = fma2(cy2, s[1], mul2(sn2, s[5])); s[5] = fma2(cy2, s[5], mul2(sp2, t));
        t = s[2]; s[2] = fma2(cy2, s[2], mul2(sn2, s[6])); s[6] = fma2(cy2, s[6], mul2(sp2, t));
        t = s[3]; s[3] = fma2(cy2, s[3], mul2(sn2, s[7])); s[7] = fma2(cy2, s[7], mul2(sp2, t));
    }
    // wire 6 (bit1): pairs (r, r^2)
    {
        const float cy = sRy[28], sy = sRy[29];
        const ull cy2 = pk(cy, cy), sp2 = pk(sy, sy), sn2 = pk(-sy, -sy);
        ull t;
        t = s[0]; s[0] = fma2(cy2, s[0], mul2(sn2, s[2])); s[2] = fma2(cy2, s[2], mul2(sp2, t));
        t = s[1]; s[1] = fma2(cy2, s[1], mul2(sn2, s[3])); s[3] = fma2(cy2, s[3], mul2(sp2, t));
        t = s[4]; s[4] = fma2(cy2, s[4], mul2(sn2, s[6])); s[6] = fma2(cy2, s[6], mul2(sp2, t));
        t = s[5]; s[5] = fma2(cy2, s[5], mul2(sn2, s[7])); s[7] = fma2(cy2, s[7], mul2(sp2, t));
    }
    // wire 7 (bit0): pairs (r, r^1)
    {
        const float cy = sRy[30], sy = sRy[31];
        const ull cy2 = pk(cy, cy), sp2 = pk(sy, sy), sn2 = pk(-sy, -sy);
        ull t;
        t = s[0]; s[0] = fma2(cy2, s[0], mul2(sn2, s[1])); s[1] = fma2(cy2, s[1], mul2(sp2, t));
        t = s[2]; s[2] = fma2(cy2, s[2], mul2(sn2, s[3])); s[3] = fma2(cy2, s[3], mul2(sp2, t));
        t = s[4]; s[4] = fma2(cy2, s[4], mul2(sn2, s[5])); s[5] = fma2(cy2, s[5], mul2(sp2, t));
        t = s[6]; s[6] = fma2(cy2, s[6], mul2(sn2, s[7])); s[7] = fma2(cy2, s[7], mul2(sp2, t));
    }
    // ---- Layer-2 RZ phases (complex multiply) ----
    #pragma unroll
    for (int r = 0; r < 8; ++r) {
        float2 ph = sPh[256 + r * 32 + lane];
        float re, im; upk(s[r], re, im);
        s[r] = pk(ph.x * re - ph.y * im, ph.x * im + ph.y * re);
    }

    // ---- CNOT chain #2: same permutation via idx shuffles ----
    {
        ull t[8];
        t[0] = myp ? s[4] : s[0];
        t[1] = myp ? s[5] : s[1];
        t[2] = myp ? s[7] : s[3];
        t[3] = myp ? s[6] : s[2];
        t[4] = myp ? s[2] : s[6];
        t[5] = myp ? s[3] : s[7];
        t[6] = myp ? s[1] : s[5];
        t[7] = myp ? s[0] : s[4];
        #pragma unroll
        for (int r = 0; r < 8; ++r) s[r] = shfl2i(t[r], psrc);
    }

    // ---- Measurements (plain index space, round-1 verified masks) ----
    float p[8], sump = 0.f;
    #pragma unroll
    for (int r = 0; r < 8; ++r) {
        float lo, hi; upk(mul2(s[r], s[r]), lo, hi);
        p[r] = lo + hi;
        sump += p[r];
    }

    float q[17];
    // Z wires 0..4: sign from lane bit (16 >> w)
    #pragma unroll
    for (int w = 0; w < 5; ++w) {
        q[w] = (lane & (1 << (4 - w))) ? -sump : sump;
    }
    // Z wires 5..7: sign from reg bit
    q[5] = (p[0] + p[1] + p[2] + p[3]) - (p[4] + p[5] + p[6] + p[7]);   // bit2
    q[6] = (p[0] + p[1] - p[2] - p[3]) + (p[4] + p[5] - p[6] - p[7]);   // bit1
    q[7] = (p[0] - p[1] + p[2] - p[3]) + (p[4] - p[5] + p[6] - p[7]);   // bit0

    // X wires 0..4: sum over all j of s_j . s_{j^lmask} (counts each pair twice)
    #pragma unroll
    for (int w = 0; w < 5; ++w) {
        const int lmask = 1 << (4 - w);
        ull acc = pk(0.f, 0.f);
        #pragma unroll
        for (int r = 0; r < 8; ++r) {
            ull bp = shfl2(s[r], lmask);
            acc = fma2(s[r], bp, acc);
        }
        float lo, hi; upk(acc, lo, hi);
        q[8 + w] = lo + hi;
    }
    // X wire 5 (bit2): pairs (r, r^4), factor 2
    {
        ull acc = fma2(s[0], s[4], mul2(s[1], s[5]));
        acc = fma2(s[2], s[6], acc);
        acc = fma2(s[3], s[7], acc);
        float lo, hi; upk(acc, lo, hi);
        q[13] = 2.f * (lo + hi);
    }
    // X wire 6 (bit1): pairs (r, r^2)
    {
        ull acc = fma2(s[0], s[2], mul2(s[1], s[3]));
        acc = fma2(s[4], s[6], acc);
        acc = fma2(s[5], s[7], acc);
        float lo, hi; upk(acc, lo, hi);
        q[14] = 2.f * (lo + hi);
    }
    // X wire 7 (bit0): pairs (r, r^1)
    {
        ull acc = fma2(s[0], s[1], mul2(s[2], s[3]));
        acc = fma2(s[4], s[5], acc);
        acc = fma2(s[6], s[7], acc);
        float lo, hi; upk(acc, lo, hi);
        q[15] = 2.f * (lo + hi);
    }
    q[16] = nrm2;

    // ---- Reduce 17 features across the warp: 2 butterfly steps + shared transpose ----
    #pragma unroll
    for (int f = 0; f < 17; ++f) {
        q[f] += __shfl_xor_sync(FULLMASK, q[f], 16);
        q[f] += __shfl_xor_sync(FULLMASK, q[f], 8);
    }
    if (lane < 8) {
        #pragma unroll
        for (int f = 0; f < 17; ++f) red[warpid][lane][f] = q[f];
    }
    __syncwarp();
    float tot = 0.f;
    if (lane < 17) {
        #pragma unroll
        for (int l = 0; l < 8; ++l) tot += red[warpid][l][lane];
    }

    // ---- BN-folded MLP, lane-parallel ----
    float nrm = __shfl_sync(FULLMASK, tot, 16);
    float inv = 1.0f / nrm;
    float qv = tot * inv;            // valid on lanes 0..15

    const int j = lane & 7;
    float acc = sb1f[j];
    #pragma unroll
    for (int f = 0; f < 16; ++f) {
        float qf = __shfl_sync(FULLMASK, qv, f);
        acc = fmaf(qf, sW1f[f * 8 + j], acc);
    }
    float h = fmaxf(acc, 0.f);
    float o0 = h * sW2[j * 2 + 0];
    float o1 = h * sW2[j * 2 + 1];
    #pragma unroll
    for (int off = 4; off > 0; off >>= 1) {
        o0 += __shfl_xor_sync(FULLMASK, o0, off);
        o1 += __shfl_xor_sync(FULLMASK, o1, off);
    }
    if (lane == 0) {
        float2* op = reinterpret_cast<float2*>(out + (size_t)sample * 2);
        *op = make_float2(o0 + sb2[0], o1 + sb2[1]);
    }
}

extern "C" void kernel_launch(void* const* d_in, const int* in_sizes, int n_in,
                              void* d_out, int out_size) {
    const float* x  = (const float*)d_in[0];
    const float* qw = (const float*)d_in[1];
    const float* g  = (const float*)d_in[2];
    const float* b  = (const float*)d_in[3];
    const float* rm = (const float*)d_in[4];
    const float* rv = (const float*)d_in[5];
    const float* W1 = (const float*)d_in[6];
    const float* b1 = (const float*)d_in[7];
    const float* W2 = (const float*)d_in[8];
    const float* b2 = (const float*)d_in[9];
    float* out = (float*)d_out;

    prep_kernel<<<1, 256>>>(qw, g, b, rm, rv, W1, b1);
    qml_kernel<<<8192, 256>>>(x, W2, b2, out);
}

// round 10
// speedup vs baseline: 1.7406x; 1.1771x over previous
#include <cuda_runtime.h>

#define FULLMASK 0xffffffffu
typedef unsigned long long ull;

// ---------------- packed f32x2 helpers ----------------
__device__ __forceinline__ ull pk(float lo, float hi) {
    ull r; asm("mov.b64 %0, {%1, %2};" : "=l"(r) : "f"(lo), "f"(hi)); return r;
}
__device__ __forceinline__ void upk(ull v, float &lo, float &hi) {
    asm("mov.b64 {%0, %1}, %2;" : "=f"(lo), "=f"(hi) : "l"(v));
}
__device__ __forceinline__ ull fma2(ull a, ull b, ull c) {
    ull d; asm("fma.rn.f32x2 %0, %1, %2, %3;" : "=l"(d) : "l"(a), "l"(b), "l"(c)); return d;
}
__device__ __forceinline__ ull mul2(ull a, ull b) {
    ull d; asm("mul.rn.f32x2 %0, %1, %2;" : "=l"(d) : "l"(a), "l"(b)); return d;
}
__device__ __forceinline__ ull shfl2(ull v, int lm) {
    float lo, hi; upk(v, lo, hi);
    lo = __shfl_xor_sync(FULLMASK, lo, lm);
    hi = __shfl_xor_sync(FULLMASK, hi, lm);
    return pk(lo, hi);
}
__device__ __forceinline__ ull shfl2i(ull v, int src) {
    float lo, hi; upk(v, lo, hi);
    lo = __shfl_sync(FULLMASK, lo, src);
    hi = __shfl_sync(FULLMASK, hi, src);
    return pk(lo, hi);
}

// ---------------- precomputed params ----------------
__device__ float  g_ry[32];      // [gate 0..15][cy,sy]
__device__ float2 g_phase[512];  // [l*256 + slot], slot = (k&15)*16 + (k>>4)
__device__ float  g_W1f[128];    // BN folded into W1
__device__ float  g_b1f[8];

__global__ void prep_kernel(const float* __restrict__ qw,
                            const float* __restrict__ g,
                            const float* __restrict__ b,
                            const float* __restrict__ rm,
                            const float* __restrict__ rv,
                            const float* __restrict__ W1,
                            const float* __restrict__ b1) {
    __shared__ float s_phi[16];
    __shared__ float s_scale[16], s_shift[16];
    int t = threadIdx.x;
    if (t < 16) {
        float sy, cy;
        sincosf(0.5f * qw[t * 2 + 0], &sy, &cy);       // RY half-angle
        g_ry[t * 2 + 0] = cy; g_ry[t * 2 + 1] = sy;
        s_phi[t] = 0.5f * qw[t * 2 + 1];               // RZ half-angle
        float sc = g[t] * rsqrtf(rv[t] + 1e-5f);
        s_scale[t] = sc;
        s_shift[t] = b[t] - rm[t] * sc;
    }
    __syncthreads();
    {
        // Plain phase tables: theta_l(k) = sum_w (bit(7-w) of k ? +phi : -phi).
        // RZs applied at end of each layer, BEFORE that layer's CNOT chain.
        int k = t;
        float th0 = 0.f, th1 = 0.f;
        #pragma unroll
        for (int w = 0; w < 8; ++w) {
            int bit = 7 - w;
            th0 += ((k >> bit) & 1) ? s_phi[w]     : -s_phi[w];
            th1 += ((k >> bit) & 1) ? s_phi[8 + w] : -s_phi[8 + w];
        }
        float c0, s0, c1, s1;
        sincosf(th0, &s0, &c0);
        sincosf(th1, &s1, &c1);
        // slot arrangement for conflict-free per-r reads: slot = (k&15)*16 + (k>>4)
        int slot = (k & 15) * 16 + (k >> 4);
        g_phase[slot]       = make_float2(c0, s0);
        g_phase[256 + slot] = make_float2(c1, s1);
    }
    if (t < 128) g_W1f[t] = s_scale[t >> 3] * W1[t];
    if (t < 8) {
        float acc = b1[t];
        #pragma unroll
        for (int kk = 0; kk < 16; ++kk) acc += s_shift[kk] * W1[kk * 8 + t];
        g_b1f[t] = acc;
    }
}

// TWO samples per warp: sample = lane bit 4 (group g), amplitude k (8 bits):
//   bits 7..4 = La = lane&15, bits 3..0 = reg r (16 complex regs per thread).
// CNOT perm new[k] = old[k^(k>>1)]: srcLane = gray4(La) (in-group),
//   src reg = gray4(rd) ^ (popc(srcLane)&1)<<3  (publish-side select).
__global__ __launch_bounds__(256, 2) void qml_kernel(const float* __restrict__ x,
                                                     const float* __restrict__ W2,
                                                     const float* __restrict__ b2,
                                                     float* __restrict__ out) {
    __shared__ float2 sPh[512];
    __shared__ float  sRy[32];
    __shared__ float  sW1f[128];
    __shared__ float  sb1f[8];
    __shared__ float  sW2[16];
    __shared__ float  sb2[2];

    int tid = threadIdx.x;
    {
        sPh[tid]       = g_phase[tid];
        sPh[tid + 256] = g_phase[tid + 256];
        if (tid < 32)        sRy[tid] = g_ry[tid];
        else if (tid < 160)  sW1f[tid - 32] = g_W1f[tid - 32];
        else if (tid < 168)  sb1f[tid - 160] = g_b1f[tid - 160];
        else if (tid < 184)  sW2[tid - 168] = W2[tid - 168];
        else if (tid < 186)  sb2[tid - 184] = b2[tid - 184];
    }
    __syncthreads();

    const int warpid = tid >> 5;
    const int lane = tid & 31;
    const int La = lane & 15;
    const int grp = lane >> 4;
    const int sample = blockIdx.x * 16 + warpid * 2 + grp;

    // Permutation constants
    const int psrc = (lane & 16) | (La ^ (La >> 1));  // gray4 within group
    const int myp  = __popc(La) & 1;

    // ---- load 16 amps (k = La*16 + idx), un-normalized ----
    const float4* xp = reinterpret_cast<const float4*>(x + (size_t)sample * 256 + La * 16);
    float a[16];
    #pragma unroll
    for (int i = 0; i < 4; ++i) {
        float4 v = xp[i];
        a[i*4+0] = v.x; a[i*4+1] = v.y; a[i*4+2] = v.z; a[i*4+3] = v.w;
    }
    float nrm2 = 0.f;
    #pragma unroll
    for (int i = 0; i < 16; ++i) nrm2 += a[i] * a[i];

    // ---- Layer 1 RYs (real). Pack (a[j], a[j+8]) -> z[j], pack dim = amp bit 3 (wire 4).
    ull z[8];
    #pragma unroll
    for (int j = 0; j < 8; ++j) z[j] = pk(a[j], a[j + 8]);

    // wires 0..3: lane-bit gates, masks 8,4,2,1 (within group)
    #pragma unroll
    for (int w = 0; w < 4; ++w) {
        const int lmask = 1 << (3 - w);
        const float cy = sRy[w * 2], sy = sRy[w * 2 + 1];
        const float se = (lane & lmask) ? sy : -sy;
        const ull cy2 = pk(cy, cy), se2 = pk(se, se);
        #pragma unroll
        for (int j = 0; j < 8; ++j)
            z[j] = fma2(cy2, z[j], mul2(se2, shfl2(z[j], lmask)));
    }
    // wire 4 (pack dim): in-reg rotate
    {
        const float cy = sRy[8], sy = sRy[9];
        #pragma unroll
        for (int j = 0; j < 8; ++j) {
            float e0, e1; upk(z[j], e0, e1);
            z[j] = pk(cy * e0 - sy * e1, sy * e0 + cy * e1);
        }
    }
    // complex-pair macro: low index (bit=0): c*lo - s*hi ; high: s*lo_old + c*hi
    #define RPAIR(arr, lo_, hi_) { ull tt = arr[lo_]; \
        arr[lo_] = fma2(cy2, arr[lo_], mul2(sn2, arr[hi_])); \
        arr[hi_] = fma2(cy2, arr[hi_], mul2(sp2, tt)); }
    // wire 5 (bit2): z pairs (j, j^4)
    {
        const float cy = sRy[10], sy = sRy[11];
        const ull cy2 = pk(cy, cy), sp2 = pk(sy, sy), sn2 = pk(-sy, -sy);
        RPAIR(z, 0, 4) RPAIR(z, 1, 5) RPAIR(z, 2, 6) RPAIR(z, 3, 7)
    }
    // wire 6 (bit1): (j, j^2)
    {
        const float cy = sRy[12], sy = sRy[13];
        const ull cy2 = pk(cy, cy), sp2 = pk(sy, sy), sn2 = pk(-sy, -sy);
        RPAIR(z, 0, 2) RPAIR(z, 1, 3) RPAIR(z, 4, 6) RPAIR(z, 5, 7)
    }
    // wire 7 (bit0): (j, j^1)
    {
        const float cy = sRy[14], sy = sRy[15];
        const ull cy2 = pk(cy, cy), sp2 = pk(sy, sy), sn2 = pk(-sy, -sy);
        RPAIR(z, 0, 1) RPAIR(z, 2, 3) RPAIR(z, 4, 5) RPAIR(z, 6, 7)
    }

    // ---- Layer-1 RZ: complexify, s[r] = a_post[r] * phase0(k) ----
    ull s[16];
    #pragma unroll
    for (int j = 0; j < 8; ++j) {
        float e0, e1; upk(z[j], e0, e1);
        float2 ph0 = sPh[j * 16 + La];
        float2 ph1 = sPh[(j + 8) * 16 + La];
        s[j]     = pk(e0 * ph0.x, e0 * ph0.y);
        s[j + 8] = pk(e1 * ph1.x, e1 * ph1.y);
    }

    // ---- CNOT chain #1 ----
    {
        ull t[16];
        if (myp) {
            t[0]=s[8];  t[1]=s[9];  t[2]=s[11]; t[3]=s[10];
            t[4]=s[14]; t[5]=s[15]; t[6]=s[13]; t[7]=s[12];
            t[8]=s[4];  t[9]=s[5];  t[10]=s[7]; t[11]=s[6];
            t[12]=s[2]; t[13]=s[3]; t[14]=s[1]; t[15]=s[0];
        } else {
            t[0]=s[0];  t[1]=s[1];  t[2]=s[3];  t[3]=s[2];
            t[4]=s[6];  t[5]=s[7];  t[6]=s[5];  t[7]=s[4];
            t[8]=s[12]; t[9]=s[13]; t[10]=s[15]; t[11]=s[14];
            t[12]=s[10]; t[13]=s[11]; t[14]=s[9]; t[15]=s[8];
        }
        #pragma unroll
        for (int r = 0; r < 16; ++r) s[r] = shfl2i(t[r], psrc);
    }

    // ---- Layer 2 RYs (complex) ----
    #pragma unroll
    for (int w = 0; w < 4; ++w) {
        const int lmask = 1 << (3 - w);
        const float cy = sRy[16 + w * 2], sy = sRy[16 + w * 2 + 1];
        const float se = (lane & lmask) ? sy : -sy;
        const ull cy2 = pk(cy, cy), se2 = pk(se, se);
        #pragma unroll
        for (int r = 0; r < 16; ++r)
            s[r] = fma2(cy2, s[r], mul2(se2, shfl2(s[r], lmask)));
    }
    // wire 4 (bit3): (r, r^8)
    {
        const float cy = sRy[24], sy = sRy[25];
        const ull cy2 = pk(cy, cy), sp2 = pk(sy, sy), sn2 = pk(-sy, -sy);
        RPAIR(s, 0, 8) RPAIR(s, 1, 9) RPAIR(s, 2, 10) RPAIR(s, 3, 11)
        RPAIR(s, 4, 12) RPAIR(s, 5, 13) RPAIR(s, 6, 14) RPAIR(s, 7, 15)
    }
    // wire 5 (bit2): (r, r^4)
    {
        const float cy = sRy[26], sy = sRy[27];
        const ull cy2 = pk(cy, cy), sp2 = pk(sy, sy), sn2 = pk(-sy, -sy);
        RPAIR(s, 0, 4) RPAIR(s, 1, 5) RPAIR(s, 2, 6) RPAIR(s, 3, 7)
        RPAIR(s, 8, 12) RPAIR(s, 9, 13) RPAIR(s, 10, 14) RPAIR(s, 11, 15)
    }
    // wire 6 (bit1): (r, r^2)
    {
        const float cy = sRy[28], sy = sRy[29];
        const ull cy2 = pk(cy, cy), sp2 = pk(sy, sy), sn2 = pk(-sy, -sy);
        RPAIR(s, 0, 2) RPAIR(s, 1, 3) RPAIR(s, 4, 6) RPAIR(s, 5, 7)
        RPAIR(s, 8, 10) RPAIR(s, 9, 11) RPAIR(s, 12, 14) RPAIR(s, 13, 15)
    }
    // wire 7 (bit0): (r, r^1)
    {
        const float cy = sRy[30], sy = sRy[31];
        const ull cy2 = pk(cy, cy), sp2 = pk(sy, sy), sn2 = pk(-sy, -sy);
        RPAIR(s, 0, 1) RPAIR(s, 2, 3) RPAIR(s, 4, 5) RPAIR(s, 6, 7)
        RPAIR(s, 8, 9) RPAIR(s, 10, 11) RPAIR(s, 12, 13) RPAIR(s, 14, 15)
    }
    // ---- Layer-2 RZ ----
    #pragma unroll
    for (int r = 0; r < 16; ++r) {
        float2 ph = sPh[256 + r * 16 + La];
        float re, im; upk(s[r], re, im);
        s[r] = pk(ph.x * re - ph.y * im, ph.x * im + ph.y * re);
    }

    // ---- CNOT chain #2 ----
    {
        ull t[16];
        if (myp) {
            t[0]=s[8];  t[1]=s[9];  t[2]=s[11]; t[3]=s[10];
            t[4]=s[14]; t[5]=s[15]; t[6]=s[13]; t[7]=s[12];
            t[8]=s[4];  t[9]=s[5];  t[10]=s[7]; t[11]=s[6];
            t[12]=s[2]; t[13]=s[3]; t[14]=s[1]; t[15]=s[0];
        } else {
            t[0]=s[0];  t[1]=s[1];  t[2]=s[3];  t[3]=s[2];
            t[4]=s[6];  t[5]=s[7];  t[6]=s[5];  t[7]=s[4];
            t[8]=s[12]; t[9]=s[13]; t[10]=s[15]; t[11]=s[14];
            t[12]=s[10]; t[13]=s[11]; t[14]=s[9]; t[15]=s[8];
        }
        #pragma unroll
        for (int r = 0; r < 16; ++r) s[r] = shfl2i(t[r], psrc);
    }

    // ---- Measurements ----
    float p[16], sump = 0.f;
    #pragma unroll
    for (int r = 0; r < 16; ++r) {
        float lo, hi; upk(mul2(s[r], s[r]), lo, hi);
        p[r] = lo + hi;
        sump += p[r];
    }

    float q[17];
    // Z wires 0..3: sign from lane bit (8 >> w)
    #pragma unroll
    for (int w = 0; w < 4; ++w)
        q[w] = (lane & (8 >> w)) ? -sump : sump;
    // Z wires 4..7: sign from reg bit 3,2,1,0
    {
        float s4 = 0.f, s5 = 0.f, s6 = 0.f, s7 = 0.f;
        #pragma unroll
        for (int r = 0; r < 16; ++r) {
            s4 += (r & 8) ? -p[r] : p[r];
            s5 += (r & 4) ? -p[r] : p[r];
            s6 += (r & 2) ? -p[r] : p[r];
            s7 += (r & 1) ? -p[r] : p[r];
        }
        q[4] = s4; q[5] = s5; q[6] = s6; q[7] = s7;
    }

    // X wires 0..3: lane masks 8,4,2,1; sum over all j counts each pair twice
    #pragma unroll
    for (int w = 0; w < 4; ++w) {
        const int lmask = 8 >> w;
        ull acc = pk(0.f, 0.f);
        #pragma unroll
        for (int r = 0; r < 16; ++r)
            acc = fma2(s[r], shfl2(s[r], lmask), acc);
        float lo, hi; upk(acc, lo, hi);
        q[8 + w] = lo + hi;
    }
    // X wire 4 (bit3): pairs (r, r^8), factor 2
    {
        ull acc = fma2(s[0], s[8], mul2(s[1], s[9]));
        acc = fma2(s[2], s[10], acc); acc = fma2(s[3], s[11], acc);
        acc = fma2(s[4], s[12], acc); acc = fma2(s[5], s[13], acc);
        acc = fma2(s[6], s[14], acc); acc = fma2(s[7], s[15], acc);
        float lo, hi; upk(acc, lo, hi);
        q[12] = 2.f * (lo + hi);
    }
    // X wire 5 (bit2): pairs (r, r^4)
    {
        ull acc = fma2(s[0], s[4], mul2(s[1], s[5]));
        acc = fma2(s[2], s[6], acc); acc = fma2(s[3], s[7], acc);
        acc = fma2(s[8], s[12], acc); acc = fma2(s[9], s[13], acc);
        acc = fma2(s[10], s[14], acc); acc = fma2(s[11], s[15], acc);
        float lo, hi; upk(acc, lo, hi);
        q[13] = 2.f * (lo + hi);
    }
    // X wire 6 (bit1): pairs (r, r^2)
    {
        ull acc = fma2(s[0], s[2], mul2(s[1], s[3]));
        acc = fma2(s[4], s[6], acc); acc = fma2(s[5], s[7], acc);
        acc = fma2(s[8], s[10], acc); acc = fma2(s[9], s[11], acc);
        acc = fma2(s[12], s[14], acc); acc = fma2(s[13], s[15], acc);
        float lo, hi; upk(acc, lo, hi);
        q[14] = 2.f * (lo + hi);
    }
    // X wire 7 (bit0): pairs (r, r^1)
    {
        ull acc = fma2(s[0], s[1], mul2(s[2], s[3]));
        acc = fma2(s[4], s[5], acc); acc = fma2(s[6], s[7], acc);
        acc = fma2(s[8], s[9], acc); acc = fma2(s[10], s[11], acc);
        acc = fma2(s[12], s[13], acc); acc = fma2(s[14], s[15], acc);
        float lo, hi; upk(acc, lo, hi);
        q[15] = 2.f * (lo + hi);
    }
    q[16] = nrm2;

    // ---- Full butterfly reduction within 16-lane group: every lane gets all totals
    #pragma unroll
    for (int f = 0; f < 17; ++f) {
        q[f] += __shfl_xor_sync(FULLMASK, q[f], 8);
        q[f] += __shfl_xor_sync(FULLMASK, q[f], 4);
        q[f] += __shfl_xor_sync(FULLMASK, q[f], 2);
        q[f] += __shfl_xor_sync(FULLMASK, q[f], 1);
    }

    // ---- BN-folded MLP, fully register-local per lane ----
    const float inv = 1.0f / q[16];
    const int j = La & 7;
    float acc = sb1f[j];
    #pragma unroll
    for (int f = 0; f < 16; ++f)
        acc = fmaf(q[f] * inv, sW1f[f * 8 + j], acc);
    float h = fmaxf(acc, 0.f);
    float o0 = h * sW2[j * 2 + 0];
    float o1 = h * sW2[j * 2 + 1];
    #pragma unroll
    for (int off = 4; off > 0; off >>= 1) {
        o0 += __shfl_xor_sync(FULLMASK, o0, off);
        o1 += __shfl_xor_sync(FULLMASK, o1, off);
    }
    if (La == 0) {
        float2* op = reinterpret_cast<float2*>(out + (size_t)sample * 2);
        *op = make_float2(o0 + sb2[0], o1 + sb2[1]);
    }
    #undef RPAIR
}

extern "C" void kernel_launch(void* const* d_in, const int* in_sizes, int n_in,
                              void* d_out, int out_size) {
    const float* x  = (const float*)d_in[0];
    const float* qw = (const float*)d_in[1];
    const float* g  = (const float*)d_in[2];
    const float* b  = (const float*)d_in[3];
    const float* rm = (const float*)d_in[4];
    const float* rv = (const float*)d_in[5];
    const float* W1 = (const float*)d_in[6];
    const float* b1 = (const float*)d_in[7];
    const float* W2 = (const float*)d_in[8];
    const float* b2 = (const float*)d_in[9];
    float* out = (float*)d_out;

    prep_kernel<<<1, 256>>>(qw, g, b, rm, rv, W1, b1);
    qml_kernel<<<4096, 256>>>(x, W2, b2, out);
}